// round 16
// baseline (speedup 1.0000x reference)
#include <cuda_runtime.h>
#include <cuda_fp16.h>
#include <stdint.h>

#define NN 100000
#define EE 3200000
#define TT 8
#define FF 64
#define NK (NN * TT)            // 800000 buckets, key = dst*8 + t
#define KBLKS (NK / 256)        // 3125

// ---------------- device scratch (allocation-free) ----------------
__device__ __half g_y[(size_t)TT * NN * FF];  // 102.4 MB: y[t*N+n][f] (fp16)
__device__ float g_hacc[(size_t)NN * FF];     // 25.6 MB fp32 partial sums
__device__ float g_h1[(size_t)NN * FF];       // 25.6 MB
__device__ unsigned int g_Vf1[16384];         // W1 fp16, mma-fragment order
__device__ unsigned int g_Vf2[16384];         // W2 fp16, mma-fragment order
__device__ int   g_pack[EE];                  // t*NN + src (payload)
__device__ int   g_key[EE];                   // dst*8 + t (sort key)
__device__ int   g_sedge[EE];                 // payload sorted by key
__device__ int   g_cnt[NK];
__device__ int   g_off[NK];
__device__ int   g_kcur[NK];
__device__ int   g_total;
__device__ int   g_mode;                      // 1 = int64 indices, 0 = int32

// ---------------- init: mode detect + zero + W->fp16 fragment pack ---------
__global__ void __launch_bounds__(256) k_init(const int* __restrict__ ei,
                                              const float* __restrict__ W1,
                                              const float* __restrict__ W2) {
    int i = blockIdx.x * 256 + threadIdx.x;
    if (i < NK) g_cnt[i] = 0;
    if (i == 0) g_total = 0;

    if (i < 32768) {
        int fi = i & 16383;
        const float* W = (i < 16384) ? W1 : W2;
        int p  = fi & 1;
        int l  = (fi >> 1) & 31;
        int nn = (fi >> 6) & 63;
        int kk = (fi >> 12) & 3;
        int k1 = kk * 16 + (l & 3) * 2 + p * 8;
        int n1 = nn * 8 + (l >> 2);
        int row = (n1 >> 6) * 64 + k1;
        float e0 = __ldg(&W[row * 64 + (n1 & 63)]);
        float e1 = __ldg(&W[(row + 1) * 64 + (n1 & 63)]);
        __half2 hv = __floats2half2_rn(e0, e1);
        unsigned int u = *(unsigned int*)&hv;
        if (i < 16384) g_Vf1[fi] = u; else g_Vf2[fi] = u;
    }

    if (blockIdx.x == 0) {
        int v = ei[2 * threadIdx.x + 1];
        unsigned int ball = __ballot_sync(0xffffffffu, v != 0);
        __shared__ int nz[8];
        if ((threadIdx.x & 31) == 0) nz[threadIdx.x >> 5] = (ball != 0);
        __syncthreads();
        if (threadIdx.x == 0) {
            int any = 0;
            for (int w = 0; w < 8; w++) any |= nz[w];
            g_mode = any ? 0 : 1;
        }
    }
}

// ---------------- HMMA gemm: y[t*N+n][fo] = x[n][:] @ W_t ------------------
__global__ void __launch_bounds__(256) k_gemm(const float* __restrict__ in,
                                              const unsigned int* __restrict__ Vf,
                                              __half* __restrict__ y) {
    __shared__ __half As[32 * 72];
    int tid = threadIdx.x;
    int nb  = blockIdx.x * 32;

    {
        int row = tid >> 3, seg = tid & 7;
        const float4* xr = (const float4*)(in + (size_t)(nb + row) * 64 + seg * 8);
        float4 f0 = __ldg(&xr[0]);
        float4 f1 = __ldg(&xr[1]);
        __half2 h0 = __floats2half2_rn(f0.x, f0.y);
        __half2 h1 = __floats2half2_rn(f0.z, f0.w);
        __half2 h2 = __floats2half2_rn(f1.x, f1.y);
        __half2 h3 = __floats2half2_rn(f1.z, f1.w);
        uint4 u;
        u.x = *(unsigned int*)&h0; u.y = *(unsigned int*)&h1;
        u.z = *(unsigned int*)&h2; u.w = *(unsigned int*)&h3;
        *(uint4*)&As[row * 72 + seg * 8] = u;
    }
    __syncthreads();

    int warpid = tid >> 5, lane = tid & 31;
    int rg = warpid >> 2;
    int cq = warpid & 3;
    int m0 = rg * 16;
    int gr = lane >> 2;
    int kc2 = (lane & 3);

    float d[16][4];
#pragma unroll
    for (int q = 0; q < 16; q++) { d[q][0] = 0.f; d[q][1] = 0.f; d[q][2] = 0.f; d[q][3] = 0.f; }

    const unsigned int* As32 = (const unsigned int*)As;
    const uint2* Bf = (const uint2*)Vf;

#pragma unroll
    for (int kk = 0; kk < 4; kk++) {
        int kw = kk * 8 + kc2;
        unsigned int a0 = As32[(m0 + gr) * 36 + kw];
        unsigned int a1 = As32[(m0 + gr + 8) * 36 + kw];
        unsigned int a2 = As32[(m0 + gr) * 36 + kw + 4];
        unsigned int a3 = As32[(m0 + gr + 8) * 36 + kw + 4];
#pragma unroll
        for (int q = 0; q < 16; q++) {
            int nn = cq * 16 + q;
            uint2 b = __ldg(&Bf[(kk * 64 + nn) * 32 + lane]);
            asm volatile(
                "mma.sync.aligned.m16n8k16.row.col.f32.f16.f16.f32 "
                "{%0,%1,%2,%3}, {%4,%5,%6,%7}, {%8,%9}, {%0,%1,%2,%3};"
                : "+f"(d[q][0]), "+f"(d[q][1]), "+f"(d[q][2]), "+f"(d[q][3])
                : "r"(a0), "r"(a1), "r"(a2), "r"(a3), "r"(b.x), "r"(b.y));
        }
    }

    __half2* y2 = (__half2*)y;
#pragma unroll
    for (int q = 0; q < 16; q++) {
        int nn = cq * 16 + q;
        int t  = nn >> 3;
        int jc = (nn & 7) * 8 + (lane & 3) * 2;
        int r0 = m0 + (lane >> 2);
        size_t base0 = ((size_t)t * NN + nb + r0) * 32 + (jc >> 1);
        size_t base1 = base0 + (size_t)8 * 32;
        y2[base0] = __floats2half2_rn(d[q][0], d[q][1]);
        y2[base1] = __floats2half2_rn(d[q][2], d[q][3]);
    }
}

// ---------------- histogram over key = dst*8+t (caches key & payload) ------
__global__ void k_hist(const void* __restrict__ ei_raw, const void* __restrict__ ti_raw) {
    int e = blockIdx.x * 256 + threadIdx.x;
    if (e >= EE) return;
    int src, dst, t;
    if (g_mode) {
        const long long* ei = (const long long*)ei_raw;
        const long long* ti = (const long long*)ti_raw;
        src = (int)ei[e];
        dst = (int)ei[(size_t)EE + e];
        t   = (int)ti[e];
    } else {
        const int* ei = (const int*)ei_raw;
        const int* ti = (const int*)ti_raw;
        src = ei[e];
        dst = ei[EE + e];
        t   = ti[e];
    }
    int key = dst * TT + t;
    g_pack[e] = t * NN + src;
    g_key[e]  = key;
    atomicAdd(&g_cnt[key], 1);
}

// ---------------- single-kernel ticketed scan over NK ----------------
__global__ void __launch_bounds__(256) k_scanA(void) {
    __shared__ int sh[256];
    __shared__ int sbase;
    int i = blockIdx.x * 256 + threadIdx.x;
    int tid = threadIdx.x;
    int v = g_cnt[i];
    sh[tid] = v;
    __syncthreads();
#pragma unroll
    for (int off = 1; off < 256; off <<= 1) {
        int u = 0;
        if (tid >= off) u = sh[tid - off];
        __syncthreads();
        if (tid >= off) sh[tid] += u;
        __syncthreads();
    }
    if (tid == 255) sbase = atomicAdd(&g_total, sh[255]);
    __syncthreads();
    int start = sbase + sh[tid] - v;
    g_off[i]  = start;
    g_kcur[i] = start;
}

// ---------------- permute: payload sorted by key ----------------
__global__ void k_permute(void) {
    int e = blockIdx.x * 256 + threadIdx.x;
    if (e >= EE) return;
    int key = __ldg(&g_key[e]);
    int pos = atomicAdd(&g_kcur[key], 1);
    g_sedge[pos] = __ldg(&g_pack[e]);
}

// ---------------- t-windowed segmented-sum pass ----------------
// Pass covers buckets {koff, koff+1} of every dst -> gathers stay inside the
// 25.6 MB y_t window (L2-resident). mode: 0=first (no hacc read),
// 1=middle (hacc RMW), 2=last (hacc read + bias + relu -> out).
__global__ void __launch_bounds__(256) k_segpass(int koff, int mode,
                                                 const __half* __restrict__ y,
                                                 const float* __restrict__ bias,
                                                 float* __restrict__ out) {
    int tid = threadIdx.x;
    int warpid = tid >> 5, lane = tid & 31;
    int eh = lane >> 4;
    int li = lane & 15;
    int d = blockIdx.x * 16 + warpid * 2 + eh;   // grid 6250 -> d < NN exactly

    int base = d * TT + koff;
    int s = __ldg(&g_off[base]);
    int2 c2 = __ldg((const int2*)&g_cnt[base]);  // base even -> aligned
    int cnt = c2.x + c2.y;                       // both buckets contiguous

    const int* se = g_sedge + s;
    const uint2* yv = (const uint2*)y;

    float4 a0 = make_float4(0.f, 0.f, 0.f, 0.f);
    float4 a1 = a0, a2 = a0, a3 = a0;
    float2 p, q;

    int e = 0;
    for (; e + 4 <= cnt; e += 4) {
        int i0 = __ldg(se + e);
        int i1 = __ldg(se + e + 1);
        int i2 = __ldg(se + e + 2);
        int i3 = __ldg(se + e + 3);
        uint2 u0 = __ldg(&yv[(size_t)i0 * 16 + li]);
        uint2 u1 = __ldg(&yv[(size_t)i1 * 16 + li]);
        uint2 u2 = __ldg(&yv[(size_t)i2 * 16 + li]);
        uint2 u3 = __ldg(&yv[(size_t)i3 * 16 + li]);
        p = __half22float2(*(__half2*)&u0.x); q = __half22float2(*(__half2*)&u0.y);
        a0.x += p.x; a0.y += p.y; a0.z += q.x; a0.w += q.y;
        p = __half22float2(*(__half2*)&u1.x); q = __half22float2(*(__half2*)&u1.y);
        a1.x += p.x; a1.y += p.y; a1.z += q.x; a1.w += q.y;
        p = __half22float2(*(__half2*)&u2.x); q = __half22float2(*(__half2*)&u2.y);
        a2.x += p.x; a2.y += p.y; a2.z += q.x; a2.w += q.y;
        p = __half22float2(*(__half2*)&u3.x); q = __half22float2(*(__half2*)&u3.y);
        a3.x += p.x; a3.y += p.y; a3.z += q.x; a3.w += q.y;
    }
    for (; e < cnt; e++) {
        int i0 = __ldg(se + e);
        uint2 u0 = __ldg(&yv[(size_t)i0 * 16 + li]);
        p = __half22float2(*(__half2*)&u0.x); q = __half22float2(*(__half2*)&u0.y);
        a0.x += p.x; a0.y += p.y; a0.z += q.x; a0.w += q.y;
    }

    a0.x += a1.x + a2.x + a3.x;
    a0.y += a1.y + a2.y + a3.y;
    a0.z += a1.z + a2.z + a3.z;
    a0.w += a1.w + a2.w + a3.w;

    float4* hacc4 = (float4*)g_hacc;
    size_t hidx = (size_t)d * 16 + li;
    if (mode != 0) {
        float4 h = hacc4[hidx];
        a0.x += h.x; a0.y += h.y; a0.z += h.z; a0.w += h.w;
    }
    if (mode == 2) {
        float4 bv = __ldg(&((const float4*)bias)[li]);
        float4 r;
        r.x = fmaxf(a0.x + bv.x, 0.f);
        r.y = fmaxf(a0.y + bv.y, 0.f);
        r.z = fmaxf(a0.z + bv.z, 0.f);
        r.w = fmaxf(a0.w + bv.w, 0.f);
        ((float4*)out)[hidx] = r;
    } else {
        hacc4[hidx] = a0;
    }
}

// ---------------- ssl = h2 @ Wssl + bssl ----------------
__global__ void __launch_bounds__(256) k_ssl(const float* __restrict__ h2,
                                             const float* __restrict__ Wssl,
                                             const float* __restrict__ bssl,
                                             float* __restrict__ out) {
    __shared__ float ws[64 * 64];
    __shared__ float hs[4 * 64];
    int tid = threadIdx.x;
    int nb  = blockIdx.x * 4;

    {
        float4* wsv = (float4*)ws;
        const float4* Wv = (const float4*)Wssl;
#pragma unroll
        for (int k = 0; k < 4; k++) wsv[tid + k * 256] = Wv[tid + k * 256];
        hs[tid] = h2[(size_t)nb * 64 + tid];
    }
    __syncthreads();

    int nl = tid >> 6;
    int fo = tid & 63;
    float a = __ldg(&bssl[fo]);
#pragma unroll 8
    for (int fin = 0; fin < 64; ++fin)
        a += hs[nl * 64 + fin] * ws[fin * 64 + fo];
    out[(size_t)(nb + nl) * 64 + fo] = a;
}

// ---------------- launch ----------------
extern "C" void kernel_launch(void* const* d_in, const int* in_sizes, int n_in,
                              void* d_out, int out_size) {
    const float* x    = (const float*)d_in[0];
    const void*  ei   = d_in[1];
    const void*  ti   = d_in[2];
    const float* W1   = (const float*)d_in[3];
    const float* b1   = (const float*)d_in[4];
    const float* W2   = (const float*)d_in[5];
    const float* b2   = (const float*)d_in[6];
    const float* Wssl = (const float*)d_in[7];
    const float* bssl = (const float*)d_in[8];
    float* out_h   = (float*)d_out;
    float* out_ssl = (float*)d_out + (size_t)NN * 64;

    unsigned int* dVf1; cudaGetSymbolAddress((void**)&dVf1, g_Vf1);
    unsigned int* dVf2; cudaGetSymbolAddress((void**)&dVf2, g_Vf2);
    __half* dy;  cudaGetSymbolAddress((void**)&dy, g_y);
    float* dh1;  cudaGetSymbolAddress((void**)&dh1, g_h1);

    // 1: init (mode detect + zero NK counters + W fragment pack)
    k_init<<<KBLKS, 256>>>((const int*)ei, W1, W2);
    // 2: HMMA gemm layer 1
    k_gemm<<<NN / 32, 256>>>(x, dVf1, dy);
    // 3-5: counting sort by (dst*8 + t)
    k_hist<<<EE / 256, 256>>>(ei, ti);
    k_scanA<<<KBLKS, 256>>>();
    k_permute<<<EE / 256, 256>>>();
    // 6-9: layer 1 t-windowed segmented sum (4 passes)
    k_segpass<<<NN / 16, 256>>>(0, 0, dy, b1, dh1);
    k_segpass<<<NN / 16, 256>>>(2, 1, dy, b1, dh1);
    k_segpass<<<NN / 16, 256>>>(4, 1, dy, b1, dh1);
    k_segpass<<<NN / 16, 256>>>(6, 2, dy, b1, dh1);
    // 10: HMMA gemm layer 2
    k_gemm<<<NN / 32, 256>>>(dh1, dVf2, dy);
    // 11-14: layer 2 segmented sum
    k_segpass<<<NN / 16, 256>>>(0, 0, dy, b2, out_h);
    k_segpass<<<NN / 16, 256>>>(2, 1, dy, b2, out_h);
    k_segpass<<<NN / 16, 256>>>(4, 1, dy, b2, out_h);
    k_segpass<<<NN / 16, 256>>>(6, 2, dy, b2, out_h);
    // 15: ssl head
    k_ssl<<<NN / 4, 256>>>(out_h, Wssl, bssl, out_ssl);
}

// round 17
// speedup vs baseline: 1.3157x; 1.3157x over previous
#include <cuda_runtime.h>
#include <cuda_fp16.h>
#include <stdint.h>

#define NN 100000
#define EE 3200000
#define TT 8
#define FF 64
#define NK (NN * TT)            // 800000 buckets, key = dst*8 + t
#define KBLKS (NK / 256)        // 3125

// ---------------- device scratch (allocation-free) ----------------
__device__ __half g_xh[(size_t)NN * FF];      // 12.8 MB fp16 input features
__device__ __half g_h1h[(size_t)NN * FF];     // 12.8 MB fp16 layer-1 output
__device__ unsigned int g_Vf1[16384];         // W1 fp16 frags: [kk8nn][lane][p]
__device__ unsigned int g_Vf2[16384];
__device__ int   g_psrc[EE];                  // cached src
__device__ int   g_key[EE];                   // dst*8 + t
__device__ int   g_sedge[EE];                 // src sorted by key
__device__ int   g_cnt[NK];
__device__ int   g_off[NK];
__device__ int   g_kcur[NK];
__device__ int   g_total;
__device__ int   g_mode;                      // 1 = int64 indices, 0 = int32

// ---------------- init: mode detect + zero + W->fp16 fragment pack ---------
// W is [512,64] row-major (k = t*64+fin, n = fo).  frag index:
// fi = ((kk*8+nn)*32 + l)*2 + p ; k1 = kk*16+(l&3)*2+p*8 ; n1 = nn*8+(l>>2)
__global__ void __launch_bounds__(256) k_init(const int* __restrict__ ei,
                                              const float* __restrict__ W1,
                                              const float* __restrict__ W2) {
    int i = blockIdx.x * 256 + threadIdx.x;
    if (i < NK) g_cnt[i] = 0;
    if (i == 0) g_total = 0;

    if (i < 32768) {
        int fi = i & 16383;
        const float* W = (i < 16384) ? W1 : W2;
        int p    = fi & 1;
        int l    = (fi >> 1) & 31;
        int tile = fi >> 6;          // 0..255
        int nn   = tile & 7;
        int kk   = tile >> 3;        // 0..31
        int k1 = kk * 16 + (l & 3) * 2 + p * 8;
        int n1 = nn * 8 + (l >> 2);
        float e0 = __ldg(&W[k1 * 64 + n1]);
        float e1 = __ldg(&W[(k1 + 1) * 64 + n1]);
        __half2 hv = __floats2half2_rn(e0, e1);
        unsigned int u = *(unsigned int*)&hv;
        if (i < 16384) g_Vf1[fi] = u; else g_Vf2[fi] = u;
    }

    if (blockIdx.x == 0) {
        int v = ei[2 * threadIdx.x + 1];
        unsigned int ball = __ballot_sync(0xffffffffu, v != 0);
        __shared__ int nz[8];
        if ((threadIdx.x & 31) == 0) nz[threadIdx.x >> 5] = (ball != 0);
        __syncthreads();
        if (threadIdx.x == 0) {
            int any = 0;
            for (int w = 0; w < 8; w++) any |= nz[w];
            g_mode = any ? 0 : 1;
        }
    }
}

// ---------------- x -> fp16 ----------------
__global__ void __launch_bounds__(256) k_xhalf(const float* __restrict__ x) {
    int i = blockIdx.x * 256 + threadIdx.x;       // 800000 threads, 8 floats each
    const float4* xr = (const float4*)x + (size_t)i * 2;
    float4 f0 = __ldg(&xr[0]);
    float4 f1 = __ldg(&xr[1]);
    __half2 h0 = __floats2half2_rn(f0.x, f0.y);
    __half2 h1 = __floats2half2_rn(f0.z, f0.w);
    __half2 h2 = __floats2half2_rn(f1.x, f1.y);
    __half2 h3 = __floats2half2_rn(f1.z, f1.w);
    uint4 u;
    u.x = *(unsigned int*)&h0; u.y = *(unsigned int*)&h1;
    u.z = *(unsigned int*)&h2; u.w = *(unsigned int*)&h3;
    ((uint4*)g_xh)[i] = u;
}

// ---------------- histogram over key = dst*8+t (caches key & src) ----------
__global__ void k_hist(const void* __restrict__ ei_raw, const void* __restrict__ ti_raw) {
    int e = blockIdx.x * 256 + threadIdx.x;
    if (e >= EE) return;
    int src, dst, t;
    if (g_mode) {
        const long long* ei = (const long long*)ei_raw;
        const long long* ti = (const long long*)ti_raw;
        src = (int)ei[e];
        dst = (int)ei[(size_t)EE + e];
        t   = (int)ti[e];
    } else {
        const int* ei = (const int*)ei_raw;
        const int* ti = (const int*)ti_raw;
        src = ei[e];
        dst = ei[EE + e];
        t   = ti[e];
    }
    int key = dst * TT + t;
    g_psrc[e] = src;
    g_key[e]  = key;
    atomicAdd(&g_cnt[key], 1);
}

// ---------------- single-kernel ticketed scan over NK ----------------
__global__ void __launch_bounds__(256) k_scanA(void) {
    __shared__ int sh[256];
    __shared__ int sbase;
    int i = blockIdx.x * 256 + threadIdx.x;
    int tid = threadIdx.x;
    int v = g_cnt[i];
    sh[tid] = v;
    __syncthreads();
#pragma unroll
    for (int off = 1; off < 256; off <<= 1) {
        int u = 0;
        if (tid >= off) u = sh[tid - off];
        __syncthreads();
        if (tid >= off) sh[tid] += u;
        __syncthreads();
    }
    if (tid == 255) sbase = atomicAdd(&g_total, sh[255]);
    __syncthreads();
    int start = sbase + sh[tid] - v;
    g_off[i]  = start;
    g_kcur[i] = start;
}

// ---------------- permute: src sorted by key ----------------
__global__ void k_permute(void) {
    int e = blockIdx.x * 256 + threadIdx.x;
    if (e >= EE) return;
    int key = __ldg(&g_key[e]);
    int pos = atomicAdd(&g_kcur[key], 1);
    g_sedge[pos] = __ldg(&g_psrc[e]);
}

// ---------------- fused: CSR aggregate (fp16 gather, L2-resident) ----------
// + HMMA GEMM [32,512]@[512,64] + bias + relu.
// Phase A: half-warp per dst (2 dsts each), per-(dst,t) float4 acc -> fp16 smem.
// Phase B: 8 warps; warp = m-tile (w>>2) x 2 n-tiles ((w&3)*2+q); K=512.
__global__ void __launch_bounds__(256) k_fused(const __half* __restrict__ in,
                                               const unsigned int* __restrict__ Vf,
                                               const float* __restrict__ bias,
                                               void* __restrict__ outp,
                                               int fp16out) {
    __shared__ __half As[32 * 520];        // 33280 B
    int tid = threadIdx.x;
    int nb = blockIdx.x * 32;

    // ---- Phase A ----
    {
        int hw = tid >> 4;                 // 16 half-warps
        int li = tid & 15;                 // uint2 column (8 halfs... no: 4 halfs)
        const uint2* x2 = (const uint2*)in;    // row = 16 uint2 (64 halfs)
#pragma unroll
        for (int p2 = 0; p2 < 2; p2++) {
            int slot = hw * 2 + p2;
            int base = (nb + slot) * TT;
            int4 o0 = __ldg((const int4*)&g_off[base]);
            int4 o1 = __ldg((const int4*)&g_off[base + 4]);
            int4 c0 = __ldg((const int4*)&g_cnt[base]);
            int4 c1 = __ldg((const int4*)&g_cnt[base + 4]);
            int st[8] = {o0.x, o0.y, o0.z, o0.w, o1.x, o1.y, o1.z, o1.w};
            int cn[8] = {c0.x, c0.y, c0.z, c0.w, c1.x, c1.y, c1.z, c1.w};
#pragma unroll
            for (int t = 0; t < TT; t++) {
                float4 acc = make_float4(0.f, 0.f, 0.f, 0.f);
                float4 acc2 = acc;
                int s = st[t], en = st[t] + cn[t];
                for (; s + 2 <= en; s += 2) {
                    int r0 = __ldg(&g_sedge[s]);
                    int r1 = __ldg(&g_sedge[s + 1]);
                    uint2 u0 = __ldg(&x2[(size_t)r0 * 16 + li]);
                    uint2 u1 = __ldg(&x2[(size_t)r1 * 16 + li]);
                    float2 p0 = __half22float2(*(__half2*)&u0.x);
                    float2 q0 = __half22float2(*(__half2*)&u0.y);
                    float2 p1 = __half22float2(*(__half2*)&u1.x);
                    float2 q1 = __half22float2(*(__half2*)&u1.y);
                    acc.x += p0.x; acc.y += p0.y; acc.z += q0.x; acc.w += q0.y;
                    acc2.x += p1.x; acc2.y += p1.y; acc2.z += q1.x; acc2.w += q1.y;
                }
                if (s < en) {
                    int r0 = __ldg(&g_sedge[s]);
                    uint2 u0 = __ldg(&x2[(size_t)r0 * 16 + li]);
                    float2 p0 = __half22float2(*(__half2*)&u0.x);
                    float2 q0 = __half22float2(*(__half2*)&u0.y);
                    acc.x += p0.x; acc.y += p0.y; acc.z += q0.x; acc.w += q0.y;
                }
                acc.x += acc2.x; acc.y += acc2.y; acc.z += acc2.z; acc.w += acc2.w;
                __half2 h0 = __floats2half2_rn(acc.x, acc.y);
                __half2 h1 = __floats2half2_rn(acc.z, acc.w);
                uint2 o;
                o.x = *(unsigned int*)&h0;
                o.y = *(unsigned int*)&h1;
                *(uint2*)&As[slot * 520 + t * 64 + li * 4] = o;
            }
        }
    }
    __syncthreads();

    // ---- Phase B: HMMA ----
    int warpid = tid >> 5, lane = tid & 31;
    int m0  = (warpid >> 2) * 16;
    int nq  = warpid & 3;
    int gr  = lane >> 2;
    int kc2 = lane & 3;

    float d[2][4];
#pragma unroll
    for (int q = 0; q < 2; q++) { d[q][0] = 0.f; d[q][1] = 0.f; d[q][2] = 0.f; d[q][3] = 0.f; }

    const unsigned int* As32 = (const unsigned int*)As;   // row stride 260
    const uint2* Bf = (const uint2*)Vf;

#pragma unroll 8
    for (int kk = 0; kk < 32; kk++) {
        int kw = kk * 8 + kc2;
        unsigned int a0 = As32[(m0 + gr) * 260 + kw];
        unsigned int a1 = As32[(m0 + gr + 8) * 260 + kw];
        unsigned int a2 = As32[(m0 + gr) * 260 + kw + 4];
        unsigned int a3 = As32[(m0 + gr + 8) * 260 + kw + 4];
#pragma unroll
        for (int q = 0; q < 2; q++) {
            int nn = nq * 2 + q;
            uint2 b = __ldg(&Bf[(kk * 8 + nn) * 32 + lane]);
            asm volatile(
                "mma.sync.aligned.m16n8k16.row.col.f32.f16.f16.f32 "
                "{%0,%1,%2,%3}, {%4,%5,%6,%7}, {%8,%9}, {%0,%1,%2,%3};"
                : "+f"(d[q][0]), "+f"(d[q][1]), "+f"(d[q][2]), "+f"(d[q][3])
                : "r"(a0), "r"(a1), "r"(a2), "r"(a3), "r"(b.x), "r"(b.y));
        }
    }

    // ---- epilogue: bias + relu; fp16 (layer1) or fp32 (layer2) out ----
#pragma unroll
    for (int q = 0; q < 2; q++) {
        int nn = nq * 2 + q;
        int col = nn * 8 + kc2 * 2;
        float2 bv = __ldg((const float2*)&bias[col]);
        int r0 = nb + m0 + gr;
        float v00 = fmaxf(d[q][0] + bv.x, 0.f);
        float v01 = fmaxf(d[q][1] + bv.y, 0.f);
        float v10 = fmaxf(d[q][2] + bv.x, 0.f);
        float v11 = fmaxf(d[q][3] + bv.y, 0.f);
        if (fp16out) {
            __half2* o2 = (__half2*)outp;
            o2[((size_t)r0 * 64 + col) >> 1]       = __floats2half2_rn(v00, v01);
            o2[((size_t)(r0 + 8) * 64 + col) >> 1] = __floats2half2_rn(v10, v11);
        } else {
            float2* o2 = (float2*)outp;
            float2 w0; w0.x = v00; w0.y = v01;
            float2 w1; w1.x = v10; w1.y = v11;
            o2[((size_t)r0 * 64 + col) >> 1]       = w0;
            o2[((size_t)(r0 + 8) * 64 + col) >> 1] = w1;
        }
    }
}

// ---------------- ssl = h2 @ Wssl + bssl ----------------
__global__ void __launch_bounds__(256) k_ssl(const float* __restrict__ h2,
                                             const float* __restrict__ Wssl,
                                             const float* __restrict__ bssl,
                                             float* __restrict__ out) {
    __shared__ float ws[64 * 64];
    __shared__ float hs[4 * 64];
    int tid = threadIdx.x;
    int nb  = blockIdx.x * 4;

    {
        float4* wsv = (float4*)ws;
        const float4* Wv = (const float4*)Wssl;
#pragma unroll
        for (int k = 0; k < 4; k++) wsv[tid + k * 256] = Wv[tid + k * 256];
        hs[tid] = h2[(size_t)nb * 64 + tid];
    }
    __syncthreads();

    int nl = tid >> 6;
    int fo = tid & 63;
    float a = __ldg(&bssl[fo]);
#pragma unroll 8
    for (int fin = 0; fin < 64; ++fin)
        a += hs[nl * 64 + fin] * ws[fin * 64 + fo];
    out[(size_t)(nb + nl) * 64 + fo] = a;
}

// ---------------- launch ----------------
extern "C" void kernel_launch(void* const* d_in, const int* in_sizes, int n_in,
                              void* d_out, int out_size) {
    const float* x    = (const float*)d_in[0];
    const void*  ei   = d_in[1];
    const void*  ti   = d_in[2];
    const float* W1   = (const float*)d_in[3];
    const float* b1   = (const float*)d_in[4];
    const float* W2   = (const float*)d_in[5];
    const float* b2   = (const float*)d_in[6];
    const float* Wssl = (const float*)d_in[7];
    const float* bssl = (const float*)d_in[8];
    float* out_h   = (float*)d_out;
    float* out_ssl = (float*)d_out + (size_t)NN * 64;

    unsigned int* dVf1; cudaGetSymbolAddress((void**)&dVf1, g_Vf1);
    unsigned int* dVf2; cudaGetSymbolAddress((void**)&dVf2, g_Vf2);
    __half* dxh;  cudaGetSymbolAddress((void**)&dxh, g_xh);
    __half* dh1h; cudaGetSymbolAddress((void**)&dh1h, g_h1h);

    // 1: init (mode detect + zero NK counters + W fragment pack)
    k_init<<<KBLKS, 256>>>((const int*)ei, W1, W2);
    // 2: x -> fp16
    k_xhalf<<<NN * 64 / (256 * 8), 256>>>(x);
    // 3-5: counting sort by (dst*8 + t), payload = src
    k_hist<<<EE / 256, 256>>>(ei, ti);
    k_scanA<<<KBLKS, 256>>>();
    k_permute<<<EE / 256, 256>>>();
    // 6: fused layer 1 -> fp16 h1
    k_fused<<<NN / 32, 256>>>(dxh, dVf1, b1, dh1h, 1);
    // 7: fused layer 2 -> fp32 out_h
    k_fused<<<NN / 32, 256>>>(dh1h, dVf2, b2, out_h, 0);
    // 8: ssl head
    k_ssl<<<NN / 4, 256>>>(out_h, Wssl, bssl, out_ssl);
}